// round 2
// baseline (speedup 1.0000x reference)
#include <cuda_runtime.h>
#include <cuda_bf16.h>
#include <cstdint>

// Problem constants
#define S_LEN   2048
#define HID     3584
#define NH      28
#define NKV     4
#define DHEAD   128
#define GROUPS  7          // NH / NKV

// Attention tiling
#define BLOCK_Q 128
#define BLOCK_K 64
#define WARPS   8
#define THREADS 256

// Smem strides (floats), chosen for conflict-free fragment LDS
#define KS_STRIDE 132      // K tile rows (64 x 132)   -> QK B-frag conflict-free
#define VS_STRIDE 136      // V tile rows (64 x 136)   -> PV B-frag conflict-free
#define PS_STRIDE 68       // P tile rows (128 x 68)   -> PV A-frag conflict-free
#define BUF_FLOATS 8704    // max(64*132, 128*68, 64*136) == 8704
#define SMEM_BYTES (2 * BUF_FLOATS * 4)

#define LOG2E 1.4426950408889634f
#define QK_SCALE 0.08838834764831845f   // 1/sqrt(128)

// TF32-rounded scratch (pre-rounded so HW truncation inside MMA is exact)
__device__ float g_qr[(size_t)NH  * S_LEN * DHEAD];  // ~29.4 MB
__device__ float g_kr[(size_t)NKV * S_LEN * DHEAD];  // ~4.2 MB

__device__ __forceinline__ float to_tf32(float x) {
    unsigned u;
    asm("cvt.rna.tf32.f32 %0, %1;" : "=r"(u) : "f"(x));
    return __uint_as_float(u);
}

__device__ __forceinline__ float fast_ex2(float x) {
    float y;
    asm("ex2.approx.ftz.f32 %0, %1;" : "=f"(y) : "f"(x));
    return y;
}

__device__ __forceinline__ void mma_tf32(float c[4], const unsigned a[4],
                                         unsigned b0, unsigned b1) {
    asm volatile(
        "mma.sync.aligned.m16n8k8.row.col.f32.tf32.tf32.f32 "
        "{%0,%1,%2,%3}, {%4,%5,%6,%7}, {%8,%9}, {%0,%1,%2,%3};\n"
        : "+f"(c[0]), "+f"(c[1]), "+f"(c[2]), "+f"(c[3])
        : "r"(a[0]), "r"(a[1]), "r"(a[2]), "r"(a[3]), "r"(b0), "r"(b1));
}

// ---------------------------------------------------------------------------
// Kernel A: RoPE for Q (with 1/sqrt(d) scale folded in) and K, TF32-rounded.
// One thread handles one (s, head, d<64) pair -> writes elements d and d+64.
// heads 0..27 -> Q, 28..31 -> KV head (hh-28).
// ---------------------------------------------------------------------------
__global__ void rope_kernel(const float* __restrict__ q,
                            const float* __restrict__ k,
                            const float* __restrict__ cosb,
                            const float* __restrict__ sinb) {
    int t = blockIdx.x * blockDim.x + threadIdx.x;
    if (t >= S_LEN * 32 * 64) return;
    int d  = t & 63;
    int hh = (t >> 6) & 31;
    int s  = t >> 11;

    float c1 = cosb[s * DHEAD + d];
    float s1 = sinb[s * DHEAD + d];
    float c2 = cosb[s * DHEAD + d + 64];
    float s2 = sinb[s * DHEAD + d + 64];

    if (hh < NH) {
        const float* src = q + (size_t)s * HID + hh * DHEAD;
        float x1 = src[d], x2 = src[d + 64];
        float o1 = (x1 * c1 - x2 * s1) * QK_SCALE;
        float o2 = (x2 * c2 + x1 * s2) * QK_SCALE;
        float* dst = g_qr + ((size_t)hh * S_LEN + s) * DHEAD;
        dst[d]      = to_tf32(o1);
        dst[d + 64] = to_tf32(o2);
    } else {
        int kvh = hh - NH;
        const float* src = k + (size_t)s * (NKV * DHEAD) + kvh * DHEAD;
        float x1 = src[d], x2 = src[d + 64];
        float* dst = g_kr + ((size_t)kvh * S_LEN + s) * DHEAD;
        dst[d]      = to_tf32(x1 * c1 - x2 * s1);
        dst[d + 64] = to_tf32(x2 * c2 + x1 * s2);
    }
}

// ---------------------------------------------------------------------------
// Kernel B: causal flash attention, tf32 mma.sync, fp32 accumulate.
// grid = (16 q-tiles, 28 heads); block = 256 threads (8 warps x 16 q-rows).
// ---------------------------------------------------------------------------
__global__ void __launch_bounds__(THREADS, 1)
attn_kernel(const float* __restrict__ v_in, float* __restrict__ out) {
    extern __shared__ float smem[];
    float* Ks = smem;                // 64 x KS_STRIDE; reused as P (128 x PS_STRIDE)
    float* Vs = smem + BUF_FLOATS;   // 64 x VS_STRIDE

    const int qt  = (gridDim.x - 1) - blockIdx.x;   // reversed: heavy tiles first
    const int h   = blockIdx.y;
    const int kvh = h / GROUPS;
    const int q0  = qt * BLOCK_Q;

    const int tid  = threadIdx.x;
    const int lane = tid & 31;
    const int w    = tid >> 5;
    const int lr   = lane >> 2;     // 0..7
    const int lc   = lane & 3;      // 0..3

    // ---- load Q fragments into registers (reused across all K tiles) ----
    const int r0 = q0 + 16 * w + lr;                 // global q row (first half)
    const float* qp = g_qr + ((size_t)h * S_LEN + r0) * DHEAD;
    unsigned qf[16][4];
#pragma unroll
    for (int kk = 0; kk < 16; kk++) {
        int c = 8 * kk + lc;
        qf[kk][0] = __float_as_uint(qp[c]);
        qf[kk][1] = __float_as_uint(qp[8 * DHEAD + c]);
        qf[kk][2] = __float_as_uint(qp[c + 4]);
        qf[kk][3] = __float_as_uint(qp[8 * DHEAD + c + 4]);
    }

    float of[16][4];
#pragma unroll
    for (int j = 0; j < 16; j++) { of[j][0]=0.f; of[j][1]=0.f; of[j][2]=0.f; of[j][3]=0.f; }
    float m0 = -1e30f, m1 = -1e30f, l0 = 0.f, l1 = 0.f;

    const int ktiles = 2 * (qt + 1);
    const float* krbase = g_kr + (size_t)kvh * S_LEN * DHEAD;

    for (int kt = 0; kt < ktiles; kt++) {
        __syncthreads();   // protect Ks(=P)/Vs from previous iteration's readers

        // ---- load K tile (already tf32) and V tile (round to tf32) ----
        {
            const float* kg = krbase + (size_t)(kt * BLOCK_K) * DHEAD;
            for (int i = tid; i < BLOCK_K * 32; i += THREADS) {
                int row = i >> 5;
                int c4  = (i & 31) << 2;
                float4 kk4 = *(const float4*)(kg + row * DHEAD + c4);
                *(float4*)(&Ks[row * KS_STRIDE + c4]) = kk4;
                float4 vv = *(const float4*)(v_in + (size_t)(kt * BLOCK_K + row) * (NKV * DHEAD)
                                             + kvh * DHEAD + c4);
                vv.x = to_tf32(vv.x); vv.y = to_tf32(vv.y);
                vv.z = to_tf32(vv.z); vv.w = to_tf32(vv.w);
                *(float4*)(&Vs[row * VS_STRIDE + c4]) = vv;
            }
        }
        __syncthreads();

        // ---- S = Q * K^T (16x64 per warp) ----
        float sf[8][4];
#pragma unroll
        for (int j = 0; j < 8; j++) { sf[j][0]=0.f; sf[j][1]=0.f; sf[j][2]=0.f; sf[j][3]=0.f; }
#pragma unroll
        for (int kk = 0; kk < 16; kk++) {
#pragma unroll
            for (int j = 0; j < 8; j++) {
                const unsigned* kp =
                    (const unsigned*)&Ks[(8 * j + lr) * KS_STRIDE + 8 * kk + lc];
                mma_tf32(sf[j], qf[kk], kp[0], kp[4]);
            }
        }

        // ---- causal mask (only possible on the last two tiles) ----
        if (kt >= 2 * qt) {
            int colb = kt * BLOCK_K + 2 * lc;
#pragma unroll
            for (int j = 0; j < 8; j++) {
                int c0 = colb + 8 * j;
                if (c0     > r0)     sf[j][0] = -1e30f;
                if (c0 + 1 > r0)     sf[j][1] = -1e30f;
                if (c0     > r0 + 8) sf[j][2] = -1e30f;
                if (c0 + 1 > r0 + 8) sf[j][3] = -1e30f;
            }
        }

        // ---- online softmax ----
        float tm0 = -1e30f, tm1 = -1e30f;
#pragma unroll
        for (int j = 0; j < 8; j++) {
            tm0 = fmaxf(tm0, fmaxf(sf[j][0], sf[j][1]));
            tm1 = fmaxf(tm1, fmaxf(sf[j][2], sf[j][3]));
        }
        tm0 = fmaxf(tm0, __shfl_xor_sync(0xffffffffu, tm0, 1));
        tm0 = fmaxf(tm0, __shfl_xor_sync(0xffffffffu, tm0, 2));
        tm1 = fmaxf(tm1, __shfl_xor_sync(0xffffffffu, tm1, 1));
        tm1 = fmaxf(tm1, __shfl_xor_sync(0xffffffffu, tm1, 2));

        float nm0 = fmaxf(m0, tm0), nm1 = fmaxf(m1, tm1);
        float sc0 = fast_ex2((m0 - nm0) * LOG2E);
        float sc1 = fast_ex2((m1 - nm1) * LOG2E);
        m0 = nm0; m1 = nm1;

        float rs0 = 0.f, rs1 = 0.f;
#pragma unroll
        for (int j = 0; j < 8; j++) {
            sf[j][0] = fast_ex2((sf[j][0] - m0) * LOG2E); rs0 += sf[j][0];
            sf[j][1] = fast_ex2((sf[j][1] - m0) * LOG2E); rs0 += sf[j][1];
            sf[j][2] = fast_ex2((sf[j][2] - m1) * LOG2E); rs1 += sf[j][2];
            sf[j][3] = fast_ex2((sf[j][3] - m1) * LOG2E); rs1 += sf[j][3];
        }
        rs0 += __shfl_xor_sync(0xffffffffu, rs0, 1);
        rs0 += __shfl_xor_sync(0xffffffffu, rs0, 2);
        rs1 += __shfl_xor_sync(0xffffffffu, rs1, 1);
        rs1 += __shfl_xor_sync(0xffffffffu, rs1, 2);
        l0 = l0 * sc0 + rs0;
        l1 = l1 * sc1 + rs1;
#pragma unroll
        for (int j = 0; j < 16; j++) {
            of[j][0] *= sc0; of[j][1] *= sc0;
            of[j][2] *= sc1; of[j][3] *= sc1;
        }

        // ---- P -> smem (C-layout -> A-layout fix-up), reusing K buffer ----
        __syncthreads();   // all warps done reading Ks before it becomes P
        {
            float* P = Ks;
            int pr = 16 * w + lr;
            int pc = 2 * lc;
#pragma unroll
            for (int j = 0; j < 8; j++) {
                float2 a = make_float2(to_tf32(sf[j][0]), to_tf32(sf[j][1]));
                float2 b = make_float2(to_tf32(sf[j][2]), to_tf32(sf[j][3]));
                *(float2*)&P[pr * PS_STRIDE + 8 * j + pc]       = a;
                *(float2*)&P[(pr + 8) * PS_STRIDE + 8 * j + pc] = b;
            }
        }
        __syncwarp();

        // ---- O += P * V ----
        {
            const float* P = Ks;
#pragma unroll
            for (int kk = 0; kk < 8; kk++) {
                unsigned af[4];
                int pa = (16 * w + lr) * PS_STRIDE + 8 * kk + lc;
                af[0] = __float_as_uint(P[pa]);
                af[1] = __float_as_uint(P[pa + 8 * PS_STRIDE]);
                af[2] = __float_as_uint(P[pa + 4]);
                af[3] = __float_as_uint(P[pa + 8 * PS_STRIDE + 4]);
#pragma unroll
                for (int jd = 0; jd < 16; jd++) {
                    int vb = (8 * kk + lc) * VS_STRIDE + 8 * jd + lr;
                    unsigned b0 = __float_as_uint(Vs[vb]);
                    unsigned b1 = __float_as_uint(Vs[vb + 4 * VS_STRIDE]);
                    mma_tf32(of[jd], af, b0, b1);
                }
            }
        }
    }

    // ---- epilogue: normalize and store ----
    float inv0 = 1.f / l0;
    float inv1 = 1.f / l1;
    float* op = out + (size_t)r0 * HID + h * DHEAD;
#pragma unroll
    for (int jd = 0; jd < 16; jd++) {
        int dc = 8 * jd + 2 * lc;
        *(float2*)&op[dc] = make_float2(of[jd][0] * inv0, of[jd][1] * inv0);
        *(float2*)&op[(size_t)8 * HID + dc] =
            make_float2(of[jd][2] * inv1, of[jd][3] * inv1);
    }
}

extern "C" void kernel_launch(void* const* d_in, const int* in_sizes, int n_in,
                              void* d_out, int out_size) {
    const float* q   = (const float*)d_in[0];
    const float* k   = (const float*)d_in[1];
    const float* v   = (const float*)d_in[2];
    const float* cs  = (const float*)d_in[3];
    const float* sn  = (const float*)d_in[4];
    // d_in[5] (attention_mask) is pure causal -> implemented analytically.

    rope_kernel<<<(S_LEN * 32 * 64) / 256, 256>>>(q, k, cs, sn);

    cudaFuncSetAttribute(attn_kernel,
                         cudaFuncAttributeMaxDynamicSharedMemorySize, SMEM_BYTES);
    dim3 grid(S_LEN / BLOCK_Q, NH);
    attn_kernel<<<grid, THREADS, SMEM_BYTES>>>(v, (float*)d_out);
}